// round 5
// baseline (speedup 1.0000x reference)
#include <cuda_runtime.h>
#include <cstdint>

#define GRID_G 128
#define RMIN_F (-1.5f)
#define STEP_F (3.0f / 128.0f)
#define VOXEL_TOTAL (8 * GRID_G * GRID_G * GRID_G * 3)   // 50331648

// ---------------------------------------------------------------------------
// Kernel 1: copy voxel_array -> out_voxel (vectorized float4)
// ---------------------------------------------------------------------------
__global__ void voxel_copy_kernel(const float4* __restrict__ src,
                                  float4* __restrict__ dst, int n4) {
    int i = blockIdx.x * blockDim.x + threadIdx.x;
    if (i < n4) dst[i] = src[i];
}

// reduction helpers (volatile, NO memory clobber: nothing in-kernel reads
// out_voxel, and ordering vs the copy kernel is at launch granularity) -------
__device__ __forceinline__ void red_add_f32(float* p, float a) {
    asm volatile("red.global.add.f32 [%0], %1;" :: "l"(p), "f"(a));
}
__device__ __forceinline__ void red_add_v2f32(float* p, float a, float b) {
    asm volatile("red.global.add.v2.f32 [%0], {%1, %2};"
                 :: "l"(p), "f"(a), "f"(b));
}

// ---------------------------------------------------------------------------
// Kernel 2: per-point trilinear gather + value write + scatter-add of diff
// Phase A: batch ALL gather loads (MLP=16)  Phase B: math  Phase C: REDs
// ---------------------------------------------------------------------------
__global__ void __launch_bounds__(256, 4)
point_kernel(const int* __restrict__ t_arr,
             const float* __restrict__ pos,
             const float* __restrict__ lr_p,
             const float* __restrict__ sigma_arr,
             const float* __restrict__ tgt,
             const float* __restrict__ voxel,
             float* __restrict__ out_value,
             float* __restrict__ out_voxel,
             int N) {
    int i = blockIdx.x * blockDim.x + threadIdx.x;
    if (i >= N) return;

    const float lr = __ldg(lr_p);

    // ---- uniform windowed input loads (pos, tgt): 2x LDG.64 each ----
    float px, py, pz, t0, t1, t2;
    int p0 = 3 * i;
    if (i < N - 1) {
        int pw = p0 & ~1;
        int qp = p0 & 1;
        float2 pa = __ldg((const float2*)(pos + pw));
        float2 pb = __ldg((const float2*)(pos + pw + 2));
        px = qp ? pa.y : pa.x;
        py = qp ? pb.x : pa.y;
        pz = qp ? pb.y : pb.x;
        float2 ga = __ldg((const float2*)(tgt + pw));
        float2 gb = __ldg((const float2*)(tgt + pw + 2));
        t0 = qp ? ga.y : ga.x;
        t1 = qp ? gb.x : ga.y;
        t2 = qp ? gb.y : gb.x;
    } else {
        px = __ldg(pos + p0 + 0); py = __ldg(pos + p0 + 1); pz = __ldg(pos + p0 + 2);
        t0 = __ldg(tgt + p0 + 0); t1 = __ldg(tgt + p0 + 1); t2 = __ldg(tgt + p0 + 2);
    }

    float sx = px - RMIN_F;
    float sy = py - RMIN_F;
    float sz = pz - RMIN_F;

    int ix = (int)floorf(sx / STEP_F);
    int iy = (int)floorf(sy / STEP_F);
    int iz = (int)floorf(sz / STEP_F);

    float u = fmodf(sx, STEP_F) / STEP_F;
    float v = fmodf(sy, STEP_F) / STEP_F;
    float w = fmodf(sz, STEP_F) / STEP_F;

    int x0 = min(max(ix,     0), GRID_G - 1);
    int x1 = min(max(ix + 1, 0), GRID_G - 1);
    int y0 = min(max(iy,     0), GRID_G - 1);
    int y1 = min(max(iy + 1, 0), GRID_G - 1);
    int z0 = min(max(iz,     0), GRID_G - 1);

    int zb = min(z0, GRID_G - 2);
    int o0 = z0 - zb;                 // 0 normally, 1 at z-top boundary

    float cu0 = 1.0f - u, cv0 = 1.0f - v, cw0 = 1.0f - w;

    // coefs, reference offset order:
    // k: (0,0,0),(1,0,0),(0,1,0),(1,1,0),(0,0,1),(1,0,1),(0,1,1),(1,1,1)
    float ck0s[4], ck1s[4];
    ck0s[0] = cu0 * cv0 * cw0;  ck1s[0] = cu0 * cv0 * w;   // (x0,y0)
    ck0s[1] = u   * cv0 * cw0;  ck1s[1] = u   * cv0 * w;   // (x1,y0)
    ck0s[2] = cu0 * v   * cw0;  ck1s[2] = cu0 * v   * w;   // (x0,y1)
    ck0s[3] = u   * v   * cw0;  ck1s[3] = u   * v   * w;   // (x1,y1)

    int base_t = t_arr[i] * (GRID_G * GRID_G * GRID_G);
    int bx0 = base_t + x0 * (GRID_G * GRID_G);
    int bx1 = base_t + x1 * (GRID_G * GRID_G);
    int bs[4];
    bs[0] = bx0 + y0 * GRID_G;
    bs[1] = bx1 + y0 * GRID_G;
    bs[2] = bx0 + y1 * GRID_G;
    bs[3] = bx1 + y1 * GRID_G;

    float sw = 1.0f - __expf(-sigma_arr[i]);
    float scale = lr * sw;

    // ---------------- Phase A: batch all gather loads ----------------
    float2 win[4][4];
    int   e_[4];
    int   q_[4];
    bool  fast_[4];
#pragma unroll
    for (int p = 0; p < 4; p++) {
        int e  = (bs[p] + zb) * 3;
        int ew = e & ~1;
        e_[p] = e;
        q_[p] = e & 1;
        bool f = (ew + 8 <= VOXEL_TOTAL);
        fast_[p] = f;
        if (f) {
            const float2* wp = (const float2*)(voxel + ew);
            win[p][0] = __ldg(wp + 0);
            win[p][1] = __ldg(wp + 1);
            win[p][2] = __ldg(wp + 2);
            win[p][3] = __ldg(wp + 3);
        }
    }

    // ---------------- Phase B+C: per-window math + REDs ----------------
    float val0 = 0.0f, val1 = 0.0f, val2 = 0.0f;
#pragma unroll
    for (int p = 0; p < 4; p++) {
        int e = e_[p];
        int q = q_[p];

        float v0x, v0y, v0z, v1x, v1y, v1z;
        if (fast_[p]) {
            float2 wa = win[p][0], wb = win[p][1], wc = win[p][2], wd = win[p][3];
            // window floats win[0..7] = wa.x wa.y wb.x wb.y wc.x wc.y wd.x wd.y
            v1x = q ? wc.x : wb.y;            // win[q+3]
            v1y = q ? wc.y : wc.x;            // win[q+4]
            v1z = q ? wd.x : wc.y;            // win[q+5]
            float b0 = q ? wa.y : wa.x;       // win[q+0]
            float b1 = q ? wb.x : wa.y;       // win[q+1]
            float b2 = q ? wb.y : wb.x;       // win[q+2]
            v0x = o0 ? v1x : b0;
            v0y = o0 ? v1y : b1;
            v0z = o0 ? v1z : b2;
        } else {
            int e0 = e + 3 * o0;
            v0x = __ldg(voxel + e0 + 0);
            v0y = __ldg(voxel + e0 + 1);
            v0z = __ldg(voxel + e0 + 2);
            v1x = __ldg(voxel + e + 3);
            v1y = __ldg(voxel + e + 4);
            v1z = __ldg(voxel + e + 5);
        }

        float ck0 = ck0s[p], ck1 = ck1s[p];
        val0 += ck0 * v0x + ck1 * v1x;
        val1 += ck0 * v0y + ck1 * v1y;
        val2 += ck0 * v0z + ck1 * v1z;

        float lam0 = __fdividef(1.0f, 1.0f + __expf(-scale * ck0));
        float lam1 = __fdividef(1.0f, 1.0f + __expf(-scale * ck1));

        float d00 = lam0 * (t0 - v0x), d01 = lam0 * (t1 - v0y), d02 = lam0 * (t2 - v0z);
        float d10 = lam1 * (t0 - v1x), d11 = lam1 * (t1 - v1y), d12 = lam1 * (t2 - v1z);

        float e00 = o0 ? 0.0f : d00;
        float e01 = o0 ? 0.0f : d01;
        float e02 = o0 ? 0.0f : d02;
        float e10 = o0 ? (d00 + d10) : d10;
        float e11 = o0 ? (d01 + d11) : d11;
        float e12 = o0 ? (d02 + d12) : d12;

        if (fast_[p]) {
            int ew = e & ~1;
            float dl0 = q ? 0.0f : e00;
            float dl1 = q ? e00  : e01;
            float dl2 = q ? e01  : e02;
            float dl3 = q ? e02  : e10;
            float dl4 = q ? e10  : e11;
            float dl5 = q ? e11  : e12;
            float dl6 = q ? e12  : 0.0f;
            float* op = out_voxel + ew;
            red_add_v2f32(op + 0, dl0, dl1);
            red_add_v2f32(op + 2, dl2, dl3);
            red_add_v2f32(op + 4, dl4, dl5);
            if (q) red_add_v2f32(op + 6, dl6, 0.0f);
        } else {
            float* op = out_voxel + e;
            red_add_f32(op + 0, e00);
            red_add_f32(op + 1, e01);
            red_add_f32(op + 2, e02);
            red_add_f32(op + 3, e10);
            red_add_f32(op + 4, e11);
            red_add_f32(op + 5, e12);
        }
    }

    out_value[p0 + 0] = val0;
    out_value[p0 + 1] = val1;
    out_value[p0 + 2] = val2;
}

// ---------------------------------------------------------------------------
// Launch
// Inputs (metadata order): t, pos, lr, sigma, target_norm, voxel_array
// Output: value (N*3 f32) followed by new_voxel (T*G*G*G*3 f32)
// ---------------------------------------------------------------------------
extern "C" void kernel_launch(void* const* d_in, const int* in_sizes, int n_in,
                              void* d_out, int out_size) {
    const int*   t_arr  = (const int*)d_in[0];
    const float* pos    = (const float*)d_in[1];
    const float* lr     = (const float*)d_in[2];
    const float* sigma  = (const float*)d_in[3];
    const float* tgt    = (const float*)d_in[4];
    const float* voxel  = (const float*)d_in[5];

    const int N = in_sizes[0];                // 1048576 points
    const int voxel_elems = in_sizes[5];      // 50331648

    float* out_value = (float*)d_out;
    float* out_voxel = out_value + (size_t)3 * N;

    // 1) copy voxel_array into output region
    {
        int n4 = voxel_elems / 4;
        int threads = 256;
        int blocks = (n4 + threads - 1) / threads;
        voxel_copy_kernel<<<blocks, threads>>>((const float4*)voxel,
                                               (float4*)out_voxel, n4);
    }

    // 2) per-point compute + scatter
    {
        int threads = 256;
        int blocks = (N + threads - 1) / threads;
        point_kernel<<<blocks, threads>>>(t_arr, pos, lr, sigma, tgt, voxel,
                                          out_value, out_voxel, N);
    }
}

// round 6
// speedup vs baseline: 1.0066x; 1.0066x over previous
#include <cuda_runtime.h>
#include <cstdint>

#define GRID_G 128
#define RMIN_F (-1.5f)
#define STEP_F (3.0f / 128.0f)
#define VOXEL_TOTAL (8 * GRID_G * GRID_G * GRID_G * 3)   // 50331648

// ---------------------------------------------------------------------------
// Kernel 1: copy voxel_array -> out_voxel (vectorized float4)
// ---------------------------------------------------------------------------
__global__ void voxel_copy_kernel(const float4* __restrict__ src,
                                  float4* __restrict__ dst, int n4) {
    int i = blockIdx.x * blockDim.x + threadIdx.x;
    if (i < n4) dst[i] = src[i];
}

// reduction helpers (no memory clobber: nothing in-kernel reads out_voxel) ---
__device__ __forceinline__ void red_add_f32(float* p, float a) {
    asm volatile("red.global.add.f32 [%0], %1;" :: "l"(p), "f"(a));
}
__device__ __forceinline__ void red_add_v2f32(float* p, float a, float b) {
    asm volatile("red.global.add.v2.f32 [%0], {%1, %2};"
                 :: "l"(p), "f"(a), "f"(b));
}

// ---------------------------------------------------------------------------
// Kernel 2: 2 threads per point. Thread h handles the two windows at
// y = (h ? y1 : y0), i.e. reference windows {(x0,y),(x1,y)}.
// ---------------------------------------------------------------------------
__global__ void __launch_bounds__(256, 5)
point_kernel(const int* __restrict__ t_arr,
             const float* __restrict__ pos,
             const float* __restrict__ lr_p,
             const float* __restrict__ sigma_arr,
             const float* __restrict__ tgt,
             const float* __restrict__ voxel,
             float* __restrict__ out_value,
             float* __restrict__ out_voxel,
             int N) {
    int tid = blockIdx.x * blockDim.x + threadIdx.x;
    int i = tid >> 1;
    if (i >= N) return;
    int h = tid & 1;

    const float lr = __ldg(lr_p);

    // ---- uniform windowed input loads (pos, tgt): 2x LDG.64 each ----
    float px, py, pz, t0, t1, t2;
    int p0 = 3 * i;
    if (i < N - 1) {
        int pw = p0 & ~1;
        int qp = p0 & 1;
        float2 pa = __ldg((const float2*)(pos + pw));
        float2 pb = __ldg((const float2*)(pos + pw + 2));
        px = qp ? pa.y : pa.x;
        py = qp ? pb.x : pa.y;
        pz = qp ? pb.y : pb.x;
        float2 ga = __ldg((const float2*)(tgt + pw));
        float2 gb = __ldg((const float2*)(tgt + pw + 2));
        t0 = qp ? ga.y : ga.x;
        t1 = qp ? gb.x : ga.y;
        t2 = qp ? gb.y : gb.x;
    } else {
        px = __ldg(pos + p0 + 0); py = __ldg(pos + p0 + 1); pz = __ldg(pos + p0 + 2);
        t0 = __ldg(tgt + p0 + 0); t1 = __ldg(tgt + p0 + 1); t2 = __ldg(tgt + p0 + 2);
    }

    float sx = px - RMIN_F;
    float sy = py - RMIN_F;
    float sz = pz - RMIN_F;

    int ix = (int)floorf(sx / STEP_F);
    int iy = (int)floorf(sy / STEP_F);
    int iz = (int)floorf(sz / STEP_F);

    float u = fmodf(sx, STEP_F) / STEP_F;
    float v = fmodf(sy, STEP_F) / STEP_F;
    float w = fmodf(sz, STEP_F) / STEP_F;

    int x0 = min(max(ix,     0), GRID_G - 1);
    int x1 = min(max(ix + 1, 0), GRID_G - 1);
    int y0 = min(max(iy,     0), GRID_G - 1);
    int y1 = min(max(iy + 1, 0), GRID_G - 1);
    int z0 = min(max(iz,     0), GRID_G - 1);

    int zb = min(z0, GRID_G - 2);
    int o0 = z0 - zb;                 // 0 normally, 1 at z-top boundary

    float cu0 = 1.0f - u, cw0 = 1.0f - w;
    float cv0 = 1.0f - v;

    // this thread's half: y index and y-coef factor
    int   yy = h ? y1 : y0;
    float cy = h ? v  : cv0;

    // two windows: (x0,yy) and (x1,yy); coefs (z-offset 0, z-offset 1)
    float ck0s[2], ck1s[2];
    ck0s[0] = cu0 * cy * cw0;  ck1s[0] = cu0 * cy * w;
    ck0s[1] = u   * cy * cw0;  ck1s[1] = u   * cy * w;

    int base_t = t_arr[i] * (GRID_G * GRID_G * GRID_G);
    int brow = base_t + yy * GRID_G;
    int bs[2];
    bs[0] = brow + x0 * (GRID_G * GRID_G);
    bs[1] = brow + x1 * (GRID_G * GRID_G);

    float sw = 1.0f - __expf(-sigma_arr[i]);
    float scale = lr * sw;

    // ---------------- Phase A: batch both windows' loads ----------------
    float2 win[2][4];
    int   e_[2];
    int   q_[2];
    bool  fast_[2];
#pragma unroll
    for (int p = 0; p < 2; p++) {
        int e  = (bs[p] + zb) * 3;
        int ew = e & ~1;
        e_[p] = e;
        q_[p] = e & 1;
        bool f = (ew + 8 <= VOXEL_TOTAL);
        fast_[p] = f;
        if (f) {
            const float2* wp = (const float2*)(voxel + ew);
            win[p][0] = __ldg(wp + 0);
            win[p][1] = __ldg(wp + 1);
            win[p][2] = __ldg(wp + 2);
            win[p][3] = __ldg(wp + 3);
        }
    }

    // ---------------- Phase B+C: per-window math + REDs ----------------
    float val0 = 0.0f, val1 = 0.0f, val2 = 0.0f;
#pragma unroll
    for (int p = 0; p < 2; p++) {
        int e = e_[p];
        int q = q_[p];

        float v0x, v0y, v0z, v1x, v1y, v1z;
        if (fast_[p]) {
            float2 wa = win[p][0], wb = win[p][1], wc = win[p][2], wd = win[p][3];
            // window floats win[0..7] = wa.x wa.y wb.x wb.y wc.x wc.y wd.x wd.y
            v1x = q ? wc.x : wb.y;            // win[q+3]
            v1y = q ? wc.y : wc.x;            // win[q+4]
            v1z = q ? wd.x : wc.y;            // win[q+5]
            float b0 = q ? wa.y : wa.x;       // win[q+0]
            float b1 = q ? wb.x : wa.y;       // win[q+1]
            float b2 = q ? wb.y : wb.x;       // win[q+2]
            v0x = o0 ? v1x : b0;
            v0y = o0 ? v1y : b1;
            v0z = o0 ? v1z : b2;
        } else {
            int e0 = e + 3 * o0;
            v0x = __ldg(voxel + e0 + 0);
            v0y = __ldg(voxel + e0 + 1);
            v0z = __ldg(voxel + e0 + 2);
            v1x = __ldg(voxel + e + 3);
            v1y = __ldg(voxel + e + 4);
            v1z = __ldg(voxel + e + 5);
        }

        float ck0 = ck0s[p], ck1 = ck1s[p];
        val0 += ck0 * v0x + ck1 * v1x;
        val1 += ck0 * v0y + ck1 * v1y;
        val2 += ck0 * v0z + ck1 * v1z;

        float lam0 = __fdividef(1.0f, 1.0f + __expf(-scale * ck0));
        float lam1 = __fdividef(1.0f, 1.0f + __expf(-scale * ck1));

        float d00 = lam0 * (t0 - v0x), d01 = lam0 * (t1 - v0y), d02 = lam0 * (t2 - v0z);
        float d10 = lam1 * (t0 - v1x), d11 = lam1 * (t1 - v1y), d12 = lam1 * (t2 - v1z);

        float e00 = o0 ? 0.0f : d00;
        float e01 = o0 ? 0.0f : d01;
        float e02 = o0 ? 0.0f : d02;
        float e10 = o0 ? (d00 + d10) : d10;
        float e11 = o0 ? (d01 + d11) : d11;
        float e12 = o0 ? (d02 + d12) : d12;

        if (fast_[p]) {
            int ew = e & ~1;
            float dl0 = q ? 0.0f : e00;
            float dl1 = q ? e00  : e01;
            float dl2 = q ? e01  : e02;
            float dl3 = q ? e02  : e10;
            float dl4 = q ? e10  : e11;
            float dl5 = q ? e11  : e12;
            float dl6 = q ? e12  : 0.0f;
            float* op = out_voxel + ew;
            red_add_v2f32(op + 0, dl0, dl1);
            red_add_v2f32(op + 2, dl2, dl3);
            red_add_v2f32(op + 4, dl4, dl5);
            if (q) red_add_v2f32(op + 6, dl6, 0.0f);
        } else {
            float* op = out_voxel + e;
            red_add_f32(op + 0, e00);
            red_add_f32(op + 1, e01);
            red_add_f32(op + 2, e02);
            red_add_f32(op + 3, e10);
            red_add_f32(op + 4, e11);
            red_add_f32(op + 5, e12);
        }
    }

    // combine value partials across the lane pair (lanes 2k / 2k+1)
    val0 += __shfl_xor_sync(0xffffffffu, val0, 1);
    val1 += __shfl_xor_sync(0xffffffffu, val1, 1);
    val2 += __shfl_xor_sync(0xffffffffu, val2, 1);
    if (h == 0) {
        out_value[p0 + 0] = val0;
        out_value[p0 + 1] = val1;
        out_value[p0 + 2] = val2;
    }
}

// ---------------------------------------------------------------------------
// Launch
// Inputs (metadata order): t, pos, lr, sigma, target_norm, voxel_array
// Output: value (N*3 f32) followed by new_voxel (T*G*G*G*3 f32)
// ---------------------------------------------------------------------------
extern "C" void kernel_launch(void* const* d_in, const int* in_sizes, int n_in,
                              void* d_out, int out_size) {
    const int*   t_arr  = (const int*)d_in[0];
    const float* pos    = (const float*)d_in[1];
    const float* lr     = (const float*)d_in[2];
    const float* sigma  = (const float*)d_in[3];
    const float* tgt    = (const float*)d_in[4];
    const float* voxel  = (const float*)d_in[5];

    const int N = in_sizes[0];                // 1048576 points
    const int voxel_elems = in_sizes[5];      // 50331648

    float* out_value = (float*)d_out;
    float* out_voxel = out_value + (size_t)3 * N;

    // 1) copy voxel_array into output region
    {
        int n4 = voxel_elems / 4;
        int threads = 256;
        int blocks = (n4 + threads - 1) / threads;
        voxel_copy_kernel<<<blocks, threads>>>((const float4*)voxel,
                                               (float4*)out_voxel, n4);
    }

    // 2) per-point compute + scatter (2 threads per point)
    {
        int threads = 256;
        long long total = 2LL * N;
        int blocks = (int)((total + threads - 1) / threads);
        point_kernel<<<blocks, threads>>>(t_arr, pos, lr, sigma, tgt, voxel,
                                          out_value, out_voxel, N);
    }
}

// round 7
// speedup vs baseline: 1.2295x; 1.2214x over previous
#include <cuda_runtime.h>
#include <cstdint>

#define GRID_G 128
#define RMIN_F (-1.5f)
#define STEP_F (3.0f / 128.0f)
#define VOXEL_TOTAL (8 * GRID_G * GRID_G * GRID_G * 3)   // 50331648

#define MAX_N   (1 << 20)
#define NB      32                      // 8 t * 4 x-high buckets
#define BSTRIDE (MAX_N / NB + 4096)     // 36864 slots per bucket

// __device__ scratch (static allocation is allowed; no cudaMalloc)
__device__ int    g_cnt[NB];
__device__ float4 g_p4[(size_t)NB * BSTRIDE];   // (pos.xyz, sigma)
__device__ float4 g_t4[(size_t)NB * BSTRIDE];   // (tgt.xyz, bitcast(orig idx))

// ---------------------------------------------------------------------------
// Kernel 0: zero bucket counters
// ---------------------------------------------------------------------------
__global__ void zero_cnt_kernel() {
    if (threadIdx.x < NB) g_cnt[threadIdx.x] = 0;
}

// ---------------------------------------------------------------------------
// Kernel 1: bucket-scatter points by (t, x-high)
// ---------------------------------------------------------------------------
__global__ void __launch_bounds__(256)
scatter_kernel(const int* __restrict__ t_arr,
               const float* __restrict__ pos,
               const float* __restrict__ sigma_arr,
               const float* __restrict__ tgt,
               int N) {
    __shared__ int s_cnt[NB];
    __shared__ int s_base[NB];
    int i = blockIdx.x * blockDim.x + threadIdx.x;
    if (threadIdx.x < NB) s_cnt[threadIdx.x] = 0;
    __syncthreads();

    int b = 0, l = 0;
    float4 p4, t4;
    bool valid = (i < N);
    if (valid) {
        float px = pos[3 * i + 0];
        float py = pos[3 * i + 1];
        float pz = pos[3 * i + 2];
        p4 = make_float4(px, py, pz, sigma_arr[i]);
        t4 = make_float4(tgt[3 * i + 0], tgt[3 * i + 1], tgt[3 * i + 2],
                         __int_as_float(i));
        int ix = (int)floorf((px - RMIN_F) / STEP_F);
        int x0 = min(max(ix, 0), GRID_G - 1);
        b = t_arr[i] * 4 + (x0 >> 5);
        l = atomicAdd(&s_cnt[b], 1);
    }
    __syncthreads();
    if (threadIdx.x < NB) {
        int c = s_cnt[threadIdx.x];
        s_base[threadIdx.x] = c ? atomicAdd(&g_cnt[threadIdx.x], c) : 0;
    }
    __syncthreads();
    if (valid) {
        int s = b * BSTRIDE + s_base[b] + l;
        g_p4[s] = p4;
        g_t4[s] = t4;
    }
}

// ---------------------------------------------------------------------------
// Kernel 2: copy voxel_array -> out_voxel (vectorized float4)
// ---------------------------------------------------------------------------
__global__ void voxel_copy_kernel(const float4* __restrict__ src,
                                  float4* __restrict__ dst, int n4) {
    int i = blockIdx.x * blockDim.x + threadIdx.x;
    if (i < n4) dst[i] = src[i];
}

// reduction helpers (no memory clobber: nothing in-kernel reads out_voxel) ---
__device__ __forceinline__ void red_add_f32(float* p, float a) {
    asm volatile("red.global.add.f32 [%0], %1;" :: "l"(p), "f"(a));
}
__device__ __forceinline__ void red_add_v2f32(float* p, float a, float b) {
    asm volatile("red.global.add.v2.f32 [%0], {%1, %2};"
                 :: "l"(p), "f"(a), "f"(b));
}

// ---------------------------------------------------------------------------
// Shared per-point body (R4 structure: 4 windows, batched loads, v2 REDs)
// ---------------------------------------------------------------------------
__device__ __forceinline__ void process_point(
    const float* __restrict__ voxel, float* __restrict__ out_voxel,
    float* __restrict__ out_value,
    float px, float py, float pz, float sigma,
    float t0, float t1, float t2, int ti, int orig, float lr)
{
    float sx = px - RMIN_F;
    float sy = py - RMIN_F;
    float sz = pz - RMIN_F;

    int ix = (int)floorf(sx / STEP_F);
    int iy = (int)floorf(sy / STEP_F);
    int iz = (int)floorf(sz / STEP_F);

    float u = fmodf(sx, STEP_F) / STEP_F;
    float v = fmodf(sy, STEP_F) / STEP_F;
    float w = fmodf(sz, STEP_F) / STEP_F;

    int x0 = min(max(ix,     0), GRID_G - 1);
    int x1 = min(max(ix + 1, 0), GRID_G - 1);
    int y0 = min(max(iy,     0), GRID_G - 1);
    int y1 = min(max(iy + 1, 0), GRID_G - 1);
    int z0 = min(max(iz,     0), GRID_G - 1);

    int zb = min(z0, GRID_G - 2);
    int o0 = z0 - zb;                 // 0 normally, 1 at z-top boundary

    float cu0 = 1.0f - u, cv0 = 1.0f - v, cw0 = 1.0f - w;

    float ck0s[4], ck1s[4];
    ck0s[0] = cu0 * cv0 * cw0;  ck1s[0] = cu0 * cv0 * w;   // (x0,y0)
    ck0s[1] = u   * cv0 * cw0;  ck1s[1] = u   * cv0 * w;   // (x1,y0)
    ck0s[2] = cu0 * v   * cw0;  ck1s[2] = cu0 * v   * w;   // (x0,y1)
    ck0s[3] = u   * v   * cw0;  ck1s[3] = u   * v   * w;   // (x1,y1)

    int base_t = ti * (GRID_G * GRID_G * GRID_G);
    int bx0 = base_t + x0 * (GRID_G * GRID_G);
    int bx1 = base_t + x1 * (GRID_G * GRID_G);
    int bs[4];
    bs[0] = bx0 + y0 * GRID_G;
    bs[1] = bx1 + y0 * GRID_G;
    bs[2] = bx0 + y1 * GRID_G;
    bs[3] = bx1 + y1 * GRID_G;

    float sw = 1.0f - __expf(-sigma);
    float scale = lr * sw;

    // Phase A: batch all gather loads (MLP)
    float2 win[4][4];
    int   e_[4];
    int   q_[4];
    bool  fast_[4];
#pragma unroll
    for (int p = 0; p < 4; p++) {
        int e  = (bs[p] + zb) * 3;
        int ew = e & ~1;
        e_[p] = e;
        q_[p] = e & 1;
        bool f = (ew + 8 <= VOXEL_TOTAL);
        fast_[p] = f;
        if (f) {
            const float2* wp = (const float2*)(voxel + ew);
            win[p][0] = __ldg(wp + 0);
            win[p][1] = __ldg(wp + 1);
            win[p][2] = __ldg(wp + 2);
            win[p][3] = __ldg(wp + 3);
        }
    }

    // Phase B+C: math + REDs
    float val0 = 0.0f, val1 = 0.0f, val2 = 0.0f;
#pragma unroll
    for (int p = 0; p < 4; p++) {
        int e = e_[p];
        int q = q_[p];

        float v0x, v0y, v0z, v1x, v1y, v1z;
        if (fast_[p]) {
            float2 wa = win[p][0], wb = win[p][1], wc = win[p][2], wd = win[p][3];
            v1x = q ? wc.x : wb.y;            // win[q+3]
            v1y = q ? wc.y : wc.x;            // win[q+4]
            v1z = q ? wd.x : wc.y;            // win[q+5]
            float b0 = q ? wa.y : wa.x;       // win[q+0]
            float b1 = q ? wb.x : wa.y;       // win[q+1]
            float b2 = q ? wb.y : wb.x;       // win[q+2]
            v0x = o0 ? v1x : b0;
            v0y = o0 ? v1y : b1;
            v0z = o0 ? v1z : b2;
        } else {
            int e0 = e + 3 * o0;
            v0x = __ldg(voxel + e0 + 0);
            v0y = __ldg(voxel + e0 + 1);
            v0z = __ldg(voxel + e0 + 2);
            v1x = __ldg(voxel + e + 3);
            v1y = __ldg(voxel + e + 4);
            v1z = __ldg(voxel + e + 5);
        }

        float ck0 = ck0s[p], ck1 = ck1s[p];
        val0 += ck0 * v0x + ck1 * v1x;
        val1 += ck0 * v0y + ck1 * v1y;
        val2 += ck0 * v0z + ck1 * v1z;

        float lam0 = __fdividef(1.0f, 1.0f + __expf(-scale * ck0));
        float lam1 = __fdividef(1.0f, 1.0f + __expf(-scale * ck1));

        float d00 = lam0 * (t0 - v0x), d01 = lam0 * (t1 - v0y), d02 = lam0 * (t2 - v0z);
        float d10 = lam1 * (t0 - v1x), d11 = lam1 * (t1 - v1y), d12 = lam1 * (t2 - v1z);

        float e00 = o0 ? 0.0f : d00;
        float e01 = o0 ? 0.0f : d01;
        float e02 = o0 ? 0.0f : d02;
        float e10 = o0 ? (d00 + d10) : d10;
        float e11 = o0 ? (d01 + d11) : d11;
        float e12 = o0 ? (d02 + d12) : d12;

        if (fast_[p]) {
            int ew = e & ~1;
            float dl0 = q ? 0.0f : e00;
            float dl1 = q ? e00  : e01;
            float dl2 = q ? e01  : e02;
            float dl3 = q ? e02  : e10;
            float dl4 = q ? e10  : e11;
            float dl5 = q ? e11  : e12;
            float dl6 = q ? e12  : 0.0f;
            float* op = out_voxel + ew;
            red_add_v2f32(op + 0, dl0, dl1);
            red_add_v2f32(op + 2, dl2, dl3);
            red_add_v2f32(op + 4, dl4, dl5);
            if (q) red_add_v2f32(op + 6, dl6, 0.0f);
        } else {
            float* op = out_voxel + e;
            red_add_f32(op + 0, e00);
            red_add_f32(op + 1, e01);
            red_add_f32(op + 2, e02);
            red_add_f32(op + 3, e10);
            red_add_f32(op + 4, e11);
            red_add_f32(op + 5, e12);
        }
    }

    out_value[3 * orig + 0] = val0;
    out_value[3 * orig + 1] = val1;
    out_value[3 * orig + 2] = val2;
}

// ---------------------------------------------------------------------------
// Kernel 3: bucketed main kernel — blocks walk buckets in order (L2 locality)
// ---------------------------------------------------------------------------
__global__ void __launch_bounds__(256, 5)
point_kernel_bucketed(const float* __restrict__ lr_p,
                      const float* __restrict__ voxel,
                      float* __restrict__ out_value,
                      float* __restrict__ out_voxel) {
    int g = blockIdx.x * blockDim.x + threadIdx.x;
    int b = g / BSTRIDE;
    int j = g - b * BSTRIDE;
    if (b >= NB || j >= g_cnt[b]) return;

    const float lr = __ldg(lr_p);
    float4 p4 = g_p4[g];
    float4 t4 = g_t4[g];
    int ti   = b >> 2;
    int orig = __float_as_int(t4.w);

    process_point(voxel, out_voxel, out_value,
                  p4.x, p4.y, p4.z, p4.w,
                  t4.x, t4.y, t4.z, ti, orig, lr);
}

// ---------------------------------------------------------------------------
// Fallback: direct (unbucketed) point kernel for N > MAX_N
// ---------------------------------------------------------------------------
__global__ void __launch_bounds__(256, 5)
point_kernel_direct(const int* __restrict__ t_arr,
                    const float* __restrict__ pos,
                    const float* __restrict__ lr_p,
                    const float* __restrict__ sigma_arr,
                    const float* __restrict__ tgt,
                    const float* __restrict__ voxel,
                    float* __restrict__ out_value,
                    float* __restrict__ out_voxel,
                    int N) {
    int i = blockIdx.x * blockDim.x + threadIdx.x;
    if (i >= N) return;
    const float lr = __ldg(lr_p);
    process_point(voxel, out_voxel, out_value,
                  pos[3 * i], pos[3 * i + 1], pos[3 * i + 2], sigma_arr[i],
                  tgt[3 * i], tgt[3 * i + 1], tgt[3 * i + 2],
                  t_arr[i], i, lr);
}

// ---------------------------------------------------------------------------
// Launch
// Inputs (metadata order): t, pos, lr, sigma, target_norm, voxel_array
// Output: value (N*3 f32) followed by new_voxel (T*G*G*G*3 f32)
// ---------------------------------------------------------------------------
extern "C" void kernel_launch(void* const* d_in, const int* in_sizes, int n_in,
                              void* d_out, int out_size) {
    const int*   t_arr  = (const int*)d_in[0];
    const float* pos    = (const float*)d_in[1];
    const float* lr     = (const float*)d_in[2];
    const float* sigma  = (const float*)d_in[3];
    const float* tgt    = (const float*)d_in[4];
    const float* voxel  = (const float*)d_in[5];

    const int N = in_sizes[0];
    const int voxel_elems = in_sizes[5];

    float* out_value = (float*)d_out;
    float* out_voxel = out_value + (size_t)3 * N;

    // copy voxel_array into output region
    {
        int n4 = voxel_elems / 4;
        int threads = 256;
        int blocks = (n4 + threads - 1) / threads;
        voxel_copy_kernel<<<blocks, threads>>>((const float4*)voxel,
                                               (float4*)out_voxel, n4);
    }

    if (N <= MAX_N) {
        zero_cnt_kernel<<<1, 32>>>();
        {
            int threads = 256;
            int blocks = (N + threads - 1) / threads;
            scatter_kernel<<<blocks, threads>>>(t_arr, pos, sigma, tgt, N);
        }
        {
            int threads = 256;
            long long total = (long long)NB * BSTRIDE;
            int blocks = (int)((total + threads - 1) / threads);
            point_kernel_bucketed<<<blocks, threads>>>(lr, voxel,
                                                       out_value, out_voxel);
        }
    } else {
        int threads = 256;
        int blocks = (N + threads - 1) / threads;
        point_kernel_direct<<<blocks, threads>>>(t_arr, pos, lr, sigma, tgt,
                                                 voxel, out_value, out_voxel, N);
    }
}

// round 8
// speedup vs baseline: 1.2918x; 1.0506x over previous
#include <cuda_runtime.h>
#include <cstdint>

#define GRID_G 128
#define RMIN_F (-1.5f)
#define STEP_F (3.0f / 128.0f)
#define VOXEL_TOTAL (8 * GRID_G * GRID_G * GRID_G * 3)   // 50331648

#define MAX_N   (1 << 20)
#define NB      32                      // 8 t * 4 x-high buckets
#define BSTRIDE (MAX_N / NB + 4096)     // 36864 slots per bucket

// __device__ scratch (static allocation; no cudaMalloc)
__device__ int    g_cnt[NB];
__device__ float4 g_p4[(size_t)NB * BSTRIDE];   // (pos.xyz, sigma)
__device__ float4 g_t4[(size_t)NB * BSTRIDE];   // (tgt.xyz, bitcast(orig idx))

// ---------------------------------------------------------------------------
// Kernel 0: zero bucket counters
// ---------------------------------------------------------------------------
__global__ void zero_cnt_kernel() {
    if (threadIdx.x < NB) g_cnt[threadIdx.x] = 0;
}

// ---------------------------------------------------------------------------
// Kernel 1: bucket-scatter points by (t, x-high)
// ---------------------------------------------------------------------------
__global__ void __launch_bounds__(256)
scatter_kernel(const int* __restrict__ t_arr,
               const float* __restrict__ pos,
               const float* __restrict__ sigma_arr,
               const float* __restrict__ tgt,
               int N) {
    __shared__ int s_cnt[NB];
    __shared__ int s_base[NB];
    int i = blockIdx.x * blockDim.x + threadIdx.x;
    if (threadIdx.x < NB) s_cnt[threadIdx.x] = 0;
    __syncthreads();

    int b = 0, l = 0;
    float4 p4, t4;
    bool valid = (i < N);
    if (valid) {
        float px = pos[3 * i + 0];
        float py = pos[3 * i + 1];
        float pz = pos[3 * i + 2];
        p4 = make_float4(px, py, pz, sigma_arr[i]);
        t4 = make_float4(tgt[3 * i + 0], tgt[3 * i + 1], tgt[3 * i + 2],
                         __int_as_float(i));
        int ix = (int)floorf((px - RMIN_F) / STEP_F);
        int x0 = min(max(ix, 0), GRID_G - 1);
        b = t_arr[i] * 4 + (x0 >> 5);
        l = atomicAdd(&s_cnt[b], 1);
    }
    __syncthreads();
    if (threadIdx.x < NB) {
        int c = s_cnt[threadIdx.x];
        s_base[threadIdx.x] = c ? atomicAdd(&g_cnt[threadIdx.x], c) : 0;
    }
    __syncthreads();
    if (valid) {
        int s = b * BSTRIDE + s_base[b] + l;
        g_p4[s] = p4;
        g_t4[s] = t4;
    }
}

// ---------------------------------------------------------------------------
// Kernel 2: copy voxel_array -> out_voxel (vectorized float4)
// ---------------------------------------------------------------------------
__global__ void voxel_copy_kernel(const float4* __restrict__ src,
                                  float4* __restrict__ dst, int n4) {
    int i = blockIdx.x * blockDim.x + threadIdx.x;
    if (i < n4) dst[i] = src[i];
}

// reduction helpers (no memory clobber: nothing in-kernel reads out_voxel) ---
__device__ __forceinline__ void red_add_f32(float* p, float a) {
    asm volatile("red.global.add.f32 [%0], %1;" :: "l"(p), "f"(a));
}
__device__ __forceinline__ void red_add_v4f32(float* p, float a, float b,
                                              float c, float d) {
    asm volatile("red.global.add.v4.f32 [%0], {%1, %2, %3, %4};"
                 :: "l"(p), "f"(a), "f"(b), "f"(c), "f"(d));
}

// ---------------------------------------------------------------------------
// Shared per-point body: 4 windows processed in 2 halves (register control).
// Each window: 12-float region at base=e&~3 (16B aligned):
//   3x LDG.128 gather, 3x red.v4.f32 scatter with zero padding.
// ---------------------------------------------------------------------------
__device__ __forceinline__ void process_point(
    const float* __restrict__ voxel, float* __restrict__ out_voxel,
    float* __restrict__ out_value,
    float px, float py, float pz, float sigma,
    float t0, float t1, float t2, int ti, int orig, float lr)
{
    float sx = px - RMIN_F;
    float sy = py - RMIN_F;
    float sz = pz - RMIN_F;

    int ix = (int)floorf(sx / STEP_F);
    int iy = (int)floorf(sy / STEP_F);
    int iz = (int)floorf(sz / STEP_F);

    float u = fmodf(sx, STEP_F) / STEP_F;
    float v = fmodf(sy, STEP_F) / STEP_F;
    float w = fmodf(sz, STEP_F) / STEP_F;

    int x0 = min(max(ix,     0), GRID_G - 1);
    int x1 = min(max(ix + 1, 0), GRID_G - 1);
    int y0 = min(max(iy,     0), GRID_G - 1);
    int y1 = min(max(iy + 1, 0), GRID_G - 1);
    int z0 = min(max(iz,     0), GRID_G - 1);

    int zb = min(z0, GRID_G - 2);
    int o0 = z0 - zb;                 // 0 normally, 1 at z-top boundary

    float cu0 = 1.0f - u, cv0 = 1.0f - v, cw0 = 1.0f - w;

    float ck0s[4], ck1s[4];
    ck0s[0] = cu0 * cv0 * cw0;  ck1s[0] = cu0 * cv0 * w;   // (x0,y0)
    ck0s[1] = u   * cv0 * cw0;  ck1s[1] = u   * cv0 * w;   // (x1,y0)
    ck0s[2] = cu0 * v   * cw0;  ck1s[2] = cu0 * v   * w;   // (x0,y1)
    ck0s[3] = u   * v   * cw0;  ck1s[3] = u   * v   * w;   // (x1,y1)

    int base_t = ti * (GRID_G * GRID_G * GRID_G);
    int bx0 = base_t + x0 * (GRID_G * GRID_G);
    int bx1 = base_t + x1 * (GRID_G * GRID_G);
    int bs[4];
    bs[0] = bx0 + y0 * GRID_G;
    bs[1] = bx1 + y0 * GRID_G;
    bs[2] = bx0 + y1 * GRID_G;
    bs[3] = bx1 + y1 * GRID_G;

    float sw = 1.0f - __expf(-sigma);
    float scale = lr * sw;

    float val0 = 0.0f, val1 = 0.0f, val2 = 0.0f;

#pragma unroll
    for (int half = 0; half < 2; half++) {
        // ---- Phase A: batch loads for 2 windows (6x LDG.128) ----
        float4 W[2][3];
        int   base_[2], off_[2];
        bool  fast_[2];
#pragma unroll
        for (int s = 0; s < 2; s++) {
            int p = 2 * half + s;
            int e    = (bs[p] + zb) * 3;
            int base = e & ~3;
            base_[s] = base;
            off_[s]  = e & 3;
            bool f = (base + 12 <= VOXEL_TOTAL);
            fast_[s] = f;
            if (f) {
                const float4* wp = (const float4*)(voxel + base);
                W[s][0] = __ldg(wp + 0);
                W[s][1] = __ldg(wp + 1);
                W[s][2] = __ldg(wp + 2);
            }
        }

        // ---- Phase B+C: math + REDs ----
#pragma unroll
        for (int s = 0; s < 2; s++) {
            int p = 2 * half + s;
            int base = base_[s];
            int off  = off_[s];
            int e    = base + off;
            bool b0 = (off & 1) != 0;
            bool b1 = (off & 2) != 0;

            float v0x, v0y, v0z, v1x, v1y, v1z;
            if (fast_[s]) {
                float wv[12];
                wv[0] = W[s][0].x; wv[1] = W[s][0].y; wv[2]  = W[s][0].z; wv[3]  = W[s][0].w;
                wv[4] = W[s][1].x; wv[5] = W[s][1].y; wv[6]  = W[s][1].z; wv[7]  = W[s][1].w;
                wv[8] = W[s][2].x; wv[9] = W[s][2].y; wv[10] = W[s][2].z; wv[11] = W[s][2].w;
                float vj[6];
#pragma unroll
                for (int j = 0; j < 6; j++) {
                    float a  = b0 ? wv[j + 1] : wv[j];
                    float bb = b0 ? wv[j + 3] : wv[j + 2];
                    vj[j] = b1 ? bb : a;
                }
                v1x = vj[3]; v1y = vj[4]; v1z = vj[5];
                v0x = o0 ? vj[3] : vj[0];
                v0y = o0 ? vj[4] : vj[1];
                v0z = o0 ? vj[5] : vj[2];
            } else {
                int e0 = e + 3 * o0;
                v0x = __ldg(voxel + e0 + 0);
                v0y = __ldg(voxel + e0 + 1);
                v0z = __ldg(voxel + e0 + 2);
                v1x = __ldg(voxel + e + 3);
                v1y = __ldg(voxel + e + 4);
                v1z = __ldg(voxel + e + 5);
            }

            float ck0 = ck0s[p], ck1 = ck1s[p];
            val0 += ck0 * v0x + ck1 * v1x;
            val1 += ck0 * v0y + ck1 * v1y;
            val2 += ck0 * v0z + ck1 * v1z;

            float lam0 = __fdividef(1.0f, 1.0f + __expf(-scale * ck0));
            float lam1 = __fdividef(1.0f, 1.0f + __expf(-scale * ck1));

            float d00 = lam0 * (t0 - v0x), d01 = lam0 * (t1 - v0y), d02 = lam0 * (t2 - v0z);
            float d10 = lam1 * (t0 - v1x), d11 = lam1 * (t1 - v1y), d12 = lam1 * (t2 - v1z);

            float E0 = o0 ? 0.0f : d00;
            float E1 = o0 ? 0.0f : d01;
            float E2 = o0 ? 0.0f : d02;
            float E3 = o0 ? (d00 + d10) : d10;
            float E4 = o0 ? (d01 + d11) : d11;
            float E5 = o0 ? (d02 + d12) : d12;

            if (fast_[s]) {
                float E[6] = {E0, E1, E2, E3, E4, E5};
                float D[12];
#pragma unroll
                for (int j = 0; j < 12; j++) {
                    float c0 = (j     >= 0 && j     <= 5) ? E[(j)     < 0 ? 0 : ((j)     > 5 ? 5 : (j))]     : 0.0f;
                    float c1 = (j - 1 >= 0 && j - 1 <= 5) ? E[(j - 1) < 0 ? 0 : ((j - 1) > 5 ? 5 : (j - 1))] : 0.0f;
                    float c2 = (j - 2 >= 0 && j - 2 <= 5) ? E[(j - 2) < 0 ? 0 : ((j - 2) > 5 ? 5 : (j - 2))] : 0.0f;
                    float c3 = (j - 3 >= 0 && j - 3 <= 5) ? E[(j - 3) < 0 ? 0 : ((j - 3) > 5 ? 5 : (j - 3))] : 0.0f;
                    float a  = b0 ? c1 : c0;
                    float bb = b0 ? c3 : c2;
                    D[j] = b1 ? bb : a;
                }
                float* op = out_voxel + base;
                red_add_v4f32(op + 0, D[0], D[1], D[2],  D[3]);
                red_add_v4f32(op + 4, D[4], D[5], D[6],  D[7]);
                red_add_v4f32(op + 8, D[8], D[9], D[10], D[11]);
            } else {
                float* op = out_voxel + e;
                red_add_f32(op + 0, E0);
                red_add_f32(op + 1, E1);
                red_add_f32(op + 2, E2);
                red_add_f32(op + 3, E3);
                red_add_f32(op + 4, E4);
                red_add_f32(op + 5, E5);
            }
        }
    }

    out_value[3 * orig + 0] = val0;
    out_value[3 * orig + 1] = val1;
    out_value[3 * orig + 2] = val2;
}

// ---------------------------------------------------------------------------
// Kernel 3: bucketed main kernel — blocks walk buckets in order (L2 locality)
// ---------------------------------------------------------------------------
__global__ void __launch_bounds__(256, 5)
point_kernel_bucketed(const float* __restrict__ lr_p,
                      const float* __restrict__ voxel,
                      float* __restrict__ out_value,
                      float* __restrict__ out_voxel) {
    int g = blockIdx.x * blockDim.x + threadIdx.x;
    int b = g / BSTRIDE;
    int j = g - b * BSTRIDE;
    if (b >= NB || j >= g_cnt[b]) return;

    const float lr = __ldg(lr_p);
    float4 p4 = g_p4[g];
    float4 t4 = g_t4[g];
    int ti   = b >> 2;
    int orig = __float_as_int(t4.w);

    process_point(voxel, out_voxel, out_value,
                  p4.x, p4.y, p4.z, p4.w,
                  t4.x, t4.y, t4.z, ti, orig, lr);
}

// ---------------------------------------------------------------------------
// Fallback: direct (unbucketed) point kernel for N > MAX_N
// ---------------------------------------------------------------------------
__global__ void __launch_bounds__(256, 5)
point_kernel_direct(const int* __restrict__ t_arr,
                    const float* __restrict__ pos,
                    const float* __restrict__ lr_p,
                    const float* __restrict__ sigma_arr,
                    const float* __restrict__ tgt,
                    const float* __restrict__ voxel,
                    float* __restrict__ out_value,
                    float* __restrict__ out_voxel,
                    int N) {
    int i = blockIdx.x * blockDim.x + threadIdx.x;
    if (i >= N) return;
    const float lr = __ldg(lr_p);
    process_point(voxel, out_voxel, out_value,
                  pos[3 * i], pos[3 * i + 1], pos[3 * i + 2], sigma_arr[i],
                  tgt[3 * i], tgt[3 * i + 1], tgt[3 * i + 2],
                  t_arr[i], i, lr);
}

// ---------------------------------------------------------------------------
// Launch
// Inputs (metadata order): t, pos, lr, sigma, target_norm, voxel_array
// Output: value (N*3 f32) followed by new_voxel (T*G*G*G*3 f32)
// ---------------------------------------------------------------------------
extern "C" void kernel_launch(void* const* d_in, const int* in_sizes, int n_in,
                              void* d_out, int out_size) {
    const int*   t_arr  = (const int*)d_in[0];
    const float* pos    = (const float*)d_in[1];
    const float* lr     = (const float*)d_in[2];
    const float* sigma  = (const float*)d_in[3];
    const float* tgt    = (const float*)d_in[4];
    const float* voxel  = (const float*)d_in[5];

    const int N = in_sizes[0];
    const int voxel_elems = in_sizes[5];

    float* out_value = (float*)d_out;
    float* out_voxel = out_value + (size_t)3 * N;

    // copy voxel_array into output region
    {
        int n4 = voxel_elems / 4;
        int threads = 256;
        int blocks = (n4 + threads - 1) / threads;
        voxel_copy_kernel<<<blocks, threads>>>((const float4*)voxel,
                                               (float4*)out_voxel, n4);
    }

    if (N <= MAX_N) {
        zero_cnt_kernel<<<1, 32>>>();
        {
            int threads = 256;
            int blocks = (N + threads - 1) / threads;
            scatter_kernel<<<blocks, threads>>>(t_arr, pos, sigma, tgt, N);
        }
        {
            int threads = 256;
            long long total = (long long)NB * BSTRIDE;
            int blocks = (int)((total + threads - 1) / threads);
            point_kernel_bucketed<<<blocks, threads>>>(lr, voxel,
                                                       out_value, out_voxel);
        }
    } else {
        int threads = 256;
        int blocks = (N + threads - 1) / threads;
        point_kernel_direct<<<blocks, threads>>>(t_arr, pos, lr, sigma, tgt,
                                                 voxel, out_value, out_voxel, N);
    }
}

// round 9
// speedup vs baseline: 1.3942x; 1.0793x over previous
#include <cuda_runtime.h>
#include <cstdint>

#define GRID_G 128
#define RMIN_F (-1.5f)
#define STEP_F (3.0f / 128.0f)
#define VOXEL_TOTAL (8 * GRID_G * GRID_G * GRID_G * 3)   // 50331648

#define MAX_N   (1 << 20)
#define NB      32                      // 8 t * 4 x-high buckets
#define BSTRIDE (MAX_N / NB + 4096)     // 36864 slots per bucket

// __device__ scratch (static allocation; no cudaMalloc)
__device__ int    g_cnt[NB];
__device__ float4 g_p4[(size_t)NB * BSTRIDE];   // (pos.xyz, sigma)
__device__ float4 g_t4[(size_t)NB * BSTRIDE];   // (tgt.xyz, bitcast(orig idx))

// ---------------------------------------------------------------------------
// Kernel 0: zero bucket counters
// ---------------------------------------------------------------------------
__global__ void zero_cnt_kernel() {
    if (threadIdx.x < NB) g_cnt[threadIdx.x] = 0;
}

// ---------------------------------------------------------------------------
// Kernel 1: bucket-scatter points by (t, x-high)
// ---------------------------------------------------------------------------
__global__ void __launch_bounds__(256)
scatter_kernel(const int* __restrict__ t_arr,
               const float* __restrict__ pos,
               const float* __restrict__ sigma_arr,
               const float* __restrict__ tgt,
               int N) {
    __shared__ int s_cnt[NB];
    __shared__ int s_base[NB];
    int i = blockIdx.x * blockDim.x + threadIdx.x;
    if (threadIdx.x < NB) s_cnt[threadIdx.x] = 0;
    __syncthreads();

    int b = 0, l = 0;
    float4 p4, t4;
    bool valid = (i < N);
    if (valid) {
        float px = pos[3 * i + 0];
        float py = pos[3 * i + 1];
        float pz = pos[3 * i + 2];
        p4 = make_float4(px, py, pz, sigma_arr[i]);
        t4 = make_float4(tgt[3 * i + 0], tgt[3 * i + 1], tgt[3 * i + 2],
                         __int_as_float(i));
        int ix = (int)floorf((px - RMIN_F) / STEP_F);
        int x0 = min(max(ix, 0), GRID_G - 1);
        b = t_arr[i] * 4 + (x0 >> 5);
        l = atomicAdd(&s_cnt[b], 1);
    }
    __syncthreads();
    if (threadIdx.x < NB) {
        int c = s_cnt[threadIdx.x];
        s_base[threadIdx.x] = c ? atomicAdd(&g_cnt[threadIdx.x], c) : 0;
    }
    __syncthreads();
    if (valid) {
        int s = b * BSTRIDE + s_base[b] + l;
        g_p4[s] = p4;
        g_t4[s] = t4;
    }
}

// ---------------------------------------------------------------------------
// Kernel 2: copy voxel_array -> out_voxel (vectorized float4)
// ---------------------------------------------------------------------------
__global__ void voxel_copy_kernel(const float4* __restrict__ src,
                                  float4* __restrict__ dst, int n4) {
    int i = blockIdx.x * blockDim.x + threadIdx.x;
    if (i < n4) dst[i] = src[i];
}

// reduction helpers (no memory clobber: nothing in-kernel reads out_voxel) ---
__device__ __forceinline__ void red_add_f32(float* p, float a) {
    asm volatile("red.global.add.f32 [%0], %1;" :: "l"(p), "f"(a));
}
__device__ __forceinline__ void red_add_v4f32(float* p, float a, float b,
                                              float c, float d) {
    asm volatile("red.global.add.v4.f32 [%0], {%1, %2, %3, %4};"
                 :: "l"(p), "f"(a), "f"(b), "f"(c), "f"(d));
}

// ---------------------------------------------------------------------------
// Shared per-point body: 4 windows in 2 halves (register control).
// Window = 6 floats at elem e, off = e&3, base = e&~3 (16B aligned).
// Slots off..off+5 fit in [0,8); slot 8 occurs only when off==3.
//   gather:  2x LDG.128 + predicated scalar LDG (off==3)
//   scatter: 2x red.v4  + predicated scalar red (off==3)
// ---------------------------------------------------------------------------
__device__ __forceinline__ void process_point(
    const float* __restrict__ voxel, float* __restrict__ out_voxel,
    float* __restrict__ out_value,
    float px, float py, float pz, float sigma,
    float t0, float t1, float t2, int ti, int orig, float lr)
{
    float sx = px - RMIN_F;
    float sy = py - RMIN_F;
    float sz = pz - RMIN_F;

    int ix = (int)floorf(sx / STEP_F);
    int iy = (int)floorf(sy / STEP_F);
    int iz = (int)floorf(sz / STEP_F);

    float u = fmodf(sx, STEP_F) / STEP_F;
    float v = fmodf(sy, STEP_F) / STEP_F;
    float w = fmodf(sz, STEP_F) / STEP_F;

    int x0 = min(max(ix,     0), GRID_G - 1);
    int x1 = min(max(ix + 1, 0), GRID_G - 1);
    int y0 = min(max(iy,     0), GRID_G - 1);
    int y1 = min(max(iy + 1, 0), GRID_G - 1);
    int z0 = min(max(iz,     0), GRID_G - 1);

    int zb = min(z0, GRID_G - 2);
    int o0 = z0 - zb;                 // 0 normally, 1 at z-top boundary

    float cu0 = 1.0f - u, cv0 = 1.0f - v, cw0 = 1.0f - w;

    float ck0s[4], ck1s[4];
    ck0s[0] = cu0 * cv0 * cw0;  ck1s[0] = cu0 * cv0 * w;   // (x0,y0)
    ck0s[1] = u   * cv0 * cw0;  ck1s[1] = u   * cv0 * w;   // (x1,y0)
    ck0s[2] = cu0 * v   * cw0;  ck1s[2] = cu0 * v   * w;   // (x0,y1)
    ck0s[3] = u   * v   * cw0;  ck1s[3] = u   * v   * w;   // (x1,y1)

    int base_t = ti * (GRID_G * GRID_G * GRID_G);
    int bx0 = base_t + x0 * (GRID_G * GRID_G);
    int bx1 = base_t + x1 * (GRID_G * GRID_G);
    int bs[4];
    bs[0] = bx0 + y0 * GRID_G;
    bs[1] = bx1 + y0 * GRID_G;
    bs[2] = bx0 + y1 * GRID_G;
    bs[3] = bx1 + y1 * GRID_G;

    float sw = 1.0f - __expf(-sigma);
    float scale = lr * sw;

    float val0 = 0.0f, val1 = 0.0f, val2 = 0.0f;

#pragma unroll
    for (int half = 0; half < 2; half++) {
        // ---- Phase A: batch loads for 2 windows ----
        float4 W[2][2];
        float  w8_[2];
        int    base_[2], off_[2];
        bool   fast_[2];
#pragma unroll
        for (int s = 0; s < 2; s++) {
            int p = 2 * half + s;
            int e    = (bs[p] + zb) * 3;
            int base = e & ~3;
            int off  = e & 3;
            base_[s] = base;
            off_[s]  = off;
            bool f = (base + 12 <= VOXEL_TOTAL);
            fast_[s] = f;
            if (f) {
                const float4* wp = (const float4*)(voxel + base);
                W[s][0] = __ldg(wp + 0);
                W[s][1] = __ldg(wp + 1);
                w8_[s] = (off == 3) ? __ldg(voxel + base + 8) : 0.0f;
            }
        }

        // ---- Phase B+C: math + REDs ----
#pragma unroll
        for (int s = 0; s < 2; s++) {
            int p = 2 * half + s;
            int base = base_[s];
            int off  = off_[s];
            int e    = base + off;
            bool b0 = (off & 1) != 0;
            bool b1 = (off & 2) != 0;

            float v0x, v0y, v0z, v1x, v1y, v1z;
            if (fast_[s]) {
                float wv[9];
                wv[0] = W[s][0].x; wv[1] = W[s][0].y; wv[2] = W[s][0].z; wv[3] = W[s][0].w;
                wv[4] = W[s][1].x; wv[5] = W[s][1].y; wv[6] = W[s][1].z; wv[7] = W[s][1].w;
                wv[8] = w8_[s];
                float vj[6];
#pragma unroll
                for (int j = 0; j < 6; j++) {
                    float a  = b0 ? wv[j + 1] : wv[j];
                    float bb = b0 ? wv[j + 3] : wv[j + 2];
                    vj[j] = b1 ? bb : a;
                }
                v1x = vj[3]; v1y = vj[4]; v1z = vj[5];
                v0x = o0 ? vj[3] : vj[0];
                v0y = o0 ? vj[4] : vj[1];
                v0z = o0 ? vj[5] : vj[2];
            } else {
                int e0 = e + 3 * o0;
                v0x = __ldg(voxel + e0 + 0);
                v0y = __ldg(voxel + e0 + 1);
                v0z = __ldg(voxel + e0 + 2);
                v1x = __ldg(voxel + e + 3);
                v1y = __ldg(voxel + e + 4);
                v1z = __ldg(voxel + e + 5);
            }

            float ck0 = ck0s[p], ck1 = ck1s[p];
            val0 += ck0 * v0x + ck1 * v1x;
            val1 += ck0 * v0y + ck1 * v1y;
            val2 += ck0 * v0z + ck1 * v1z;

            float lam0 = __fdividef(1.0f, 1.0f + __expf(-scale * ck0));
            float lam1 = __fdividef(1.0f, 1.0f + __expf(-scale * ck1));

            float d00 = lam0 * (t0 - v0x), d01 = lam0 * (t1 - v0y), d02 = lam0 * (t2 - v0z);
            float d10 = lam1 * (t0 - v1x), d11 = lam1 * (t1 - v1y), d12 = lam1 * (t2 - v1z);

            float E0 = o0 ? 0.0f : d00;
            float E1 = o0 ? 0.0f : d01;
            float E2 = o0 ? 0.0f : d02;
            float E3 = o0 ? (d00 + d10) : d10;
            float E4 = o0 ? (d01 + d11) : d11;
            float E5 = o0 ? (d02 + d12) : d12;

            if (fast_[s]) {
                float E[6] = {E0, E1, E2, E3, E4, E5};
                // D[j] = (0 <= j-off <= 5) ? E[j-off] : 0, for j in 0..7
                float D[8];
#pragma unroll
                for (int j = 0; j < 8; j++) {
                    float c0 = (j <= 5)            ? E[j > 5 ? 5 : j]                 : 0.0f;
                    float c1 = (j >= 1 && j <= 6)  ? E[(j - 1) > 5 ? 5 : (j - 1)]     : 0.0f;
                    float c2 = (j >= 2 && j <= 7)  ? E[(j - 2) > 5 ? 5 : (j - 2)]     : 0.0f;
                    float c3 = (j >= 3)            ? E[(j - 3) > 5 ? 5 : (j - 3)]     : 0.0f;
                    float a  = b0 ? c1 : c0;
                    float bb = b0 ? c3 : c2;
                    D[j] = b1 ? bb : a;
                }
                float* op = out_voxel + base;
                red_add_v4f32(op + 0, D[0], D[1], D[2], D[3]);
                red_add_v4f32(op + 4, D[4], D[5], D[6], D[7]);
                if (off == 3) red_add_f32(op + 8, E5);
            } else {
                float* op = out_voxel + e;
                red_add_f32(op + 0, E0);
                red_add_f32(op + 1, E1);
                red_add_f32(op + 2, E2);
                red_add_f32(op + 3, E3);
                red_add_f32(op + 4, E4);
                red_add_f32(op + 5, E5);
            }
        }
    }

    out_value[3 * orig + 0] = val0;
    out_value[3 * orig + 1] = val1;
    out_value[3 * orig + 2] = val2;
}

// ---------------------------------------------------------------------------
// Kernel 3: bucketed main kernel — blocks walk buckets in order (L2 locality)
// ---------------------------------------------------------------------------
__global__ void __launch_bounds__(256, 5)
point_kernel_bucketed(const float* __restrict__ lr_p,
                      const float* __restrict__ voxel,
                      float* __restrict__ out_value,
                      float* __restrict__ out_voxel) {
    int g = blockIdx.x * blockDim.x + threadIdx.x;
    int b = g / BSTRIDE;
    int j = g - b * BSTRIDE;
    if (b >= NB || j >= g_cnt[b]) return;

    const float lr = __ldg(lr_p);
    float4 p4 = g_p4[g];
    float4 t4 = g_t4[g];
    int ti   = b >> 2;
    int orig = __float_as_int(t4.w);

    process_point(voxel, out_voxel, out_value,
                  p4.x, p4.y, p4.z, p4.w,
                  t4.x, t4.y, t4.z, ti, orig, lr);
}

// ---------------------------------------------------------------------------
// Fallback: direct (unbucketed) point kernel for N > MAX_N
// ---------------------------------------------------------------------------
__global__ void __launch_bounds__(256, 5)
point_kernel_direct(const int* __restrict__ t_arr,
                    const float* __restrict__ pos,
                    const float* __restrict__ lr_p,
                    const float* __restrict__ sigma_arr,
                    const float* __restrict__ tgt,
                    const float* __restrict__ voxel,
                    float* __restrict__ out_value,
                    float* __restrict__ out_voxel,
                    int N) {
    int i = blockIdx.x * blockDim.x + threadIdx.x;
    if (i >= N) return;
    const float lr = __ldg(lr_p);
    process_point(voxel, out_voxel, out_value,
                  pos[3 * i], pos[3 * i + 1], pos[3 * i + 2], sigma_arr[i],
                  tgt[3 * i], tgt[3 * i + 1], tgt[3 * i + 2],
                  t_arr[i], i, lr);
}

// ---------------------------------------------------------------------------
// Launch
// Inputs (metadata order): t, pos, lr, sigma, target_norm, voxel_array
// Output: value (N*3 f32) followed by new_voxel (T*G*G*G*3 f32)
// ---------------------------------------------------------------------------
extern "C" void kernel_launch(void* const* d_in, const int* in_sizes, int n_in,
                              void* d_out, int out_size) {
    const int*   t_arr  = (const int*)d_in[0];
    const float* pos    = (const float*)d_in[1];
    const float* lr     = (const float*)d_in[2];
    const float* sigma  = (const float*)d_in[3];
    const float* tgt    = (const float*)d_in[4];
    const float* voxel  = (const float*)d_in[5];

    const int N = in_sizes[0];
    const int voxel_elems = in_sizes[5];

    float* out_value = (float*)d_out;
    float* out_voxel = out_value + (size_t)3 * N;

    // copy voxel_array into output region
    {
        int n4 = voxel_elems / 4;
        int threads = 256;
        int blocks = (n4 + threads - 1) / threads;
        voxel_copy_kernel<<<blocks, threads>>>((const float4*)voxel,
                                               (float4*)out_voxel, n4);
    }

    if (N <= MAX_N) {
        zero_cnt_kernel<<<1, 32>>>();
        {
            int threads = 256;
            int blocks = (N + threads - 1) / threads;
            scatter_kernel<<<blocks, threads>>>(t_arr, pos, sigma, tgt, N);
        }
        {
            int threads = 256;
            long long total = (long long)NB * BSTRIDE;
            int blocks = (int)((total + threads - 1) / threads);
            point_kernel_bucketed<<<blocks, threads>>>(lr, voxel,
                                                       out_value, out_voxel);
        }
    } else {
        int threads = 256;
        int blocks = (N + threads - 1) / threads;
        point_kernel_direct<<<blocks, threads>>>(t_arr, pos, lr, sigma, tgt,
                                                 voxel, out_value, out_voxel, N);
    }
}

// round 10
// speedup vs baseline: 1.4101x; 1.0114x over previous
#include <cuda_runtime.h>
#include <cstdint>

#define GRID_G 128
#define RMIN_F (-1.5f)
#define STEP_F (3.0f / 128.0f)
#define VOXEL_TOTAL (8 * GRID_G * GRID_G * GRID_G * 3)   // 50331648

#define MAX_N   (1 << 20)
#define NB      32                      // 8 t * 4 x-high buckets
#define BSTRIDE (MAX_N / NB + 4096)     // 36864 slots per bucket

// __device__ scratch (static allocation; no cudaMalloc)
__device__ int    g_cnt[NB];
__device__ float4 g_p4[(size_t)NB * BSTRIDE];   // (pos.xyz, sigma)
__device__ float4 g_t4[(size_t)NB * BSTRIDE];   // (tgt.xyz, bitcast(orig idx))

// ---------------------------------------------------------------------------
// Kernel 0: zero bucket counters
// ---------------------------------------------------------------------------
__global__ void zero_cnt_kernel() {
    if (threadIdx.x < NB) g_cnt[threadIdx.x] = 0;
}

// ---------------------------------------------------------------------------
// Kernel 1 (fused): blocks [0, SB) bucket-scatter the points; blocks [SB, ...)
// copy voxel_array -> out_voxel (float4). Scatter blocks scheduled first so
// their latency hides under the DRAM-bound copy.
// ---------------------------------------------------------------------------
__global__ void __launch_bounds__(256)
copy_and_scatter_kernel(const int* __restrict__ t_arr,
                        const float* __restrict__ pos,
                        const float* __restrict__ sigma_arr,
                        const float* __restrict__ tgt,
                        const float4* __restrict__ vsrc,
                        float4* __restrict__ vdst,
                        int N, int SB, int n4) {
    __shared__ int s_cnt[NB];
    __shared__ int s_base[NB];

    if (blockIdx.x >= SB) {
        // ---- copy path ----
        int i = (blockIdx.x - SB) * blockDim.x + threadIdx.x;
        if (i < n4) vdst[i] = vsrc[i];
        return;
    }

    // ---- scatter path ----
    int i = blockIdx.x * blockDim.x + threadIdx.x;
    if (threadIdx.x < NB) s_cnt[threadIdx.x] = 0;
    __syncthreads();

    int b = 0, l = 0;
    float4 p4, t4;
    bool valid = (i < N);
    if (valid) {
        float px = pos[3 * i + 0];
        float py = pos[3 * i + 1];
        float pz = pos[3 * i + 2];
        p4 = make_float4(px, py, pz, sigma_arr[i]);
        t4 = make_float4(tgt[3 * i + 0], tgt[3 * i + 1], tgt[3 * i + 2],
                         __int_as_float(i));
        int ix = (int)floorf((px - RMIN_F) / STEP_F);
        int x0 = min(max(ix, 0), GRID_G - 1);
        b = t_arr[i] * 4 + (x0 >> 5);
        l = atomicAdd(&s_cnt[b], 1);
    }
    __syncthreads();
    if (threadIdx.x < NB) {
        int c = s_cnt[threadIdx.x];
        s_base[threadIdx.x] = c ? atomicAdd(&g_cnt[threadIdx.x], c) : 0;
    }
    __syncthreads();
    if (valid) {
        int s = b * BSTRIDE + s_base[b] + l;
        g_p4[s] = p4;
        g_t4[s] = t4;
    }
}

// reduction helpers (no memory clobber: nothing in-kernel reads out_voxel) ---
__device__ __forceinline__ void red_add_f32(float* p, float a) {
    asm volatile("red.global.add.f32 [%0], %1;" :: "l"(p), "f"(a));
}
__device__ __forceinline__ void red_add_v4f32(float* p, float a, float b,
                                              float c, float d) {
    asm volatile("red.global.add.v4.f32 [%0], {%1, %2, %3, %4};"
                 :: "l"(p), "f"(a), "f"(b), "f"(c), "f"(d));
}

// ---------------------------------------------------------------------------
// Shared per-point body: 4 windows in 2 halves (register control).
// Window = 6 floats at elem e, off = e&3, base = e&~3 (16B aligned).
//   gather:  2x LDG.128 + predicated scalar LDG (off==3)
//   scatter: 2x red.v4  + predicated scalar red (off==3)
// ---------------------------------------------------------------------------
__device__ __forceinline__ void process_point(
    const float* __restrict__ voxel, float* __restrict__ out_voxel,
    float* __restrict__ out_value,
    float px, float py, float pz, float sigma,
    float t0, float t1, float t2, int ti, int orig, float lr)
{
    float sx = px - RMIN_F;
    float sy = py - RMIN_F;
    float sz = pz - RMIN_F;

    int ix = (int)floorf(sx / STEP_F);
    int iy = (int)floorf(sy / STEP_F);
    int iz = (int)floorf(sz / STEP_F);

    float u = fmodf(sx, STEP_F) / STEP_F;
    float v = fmodf(sy, STEP_F) / STEP_F;
    float w = fmodf(sz, STEP_F) / STEP_F;

    int x0 = min(max(ix,     0), GRID_G - 1);
    int x1 = min(max(ix + 1, 0), GRID_G - 1);
    int y0 = min(max(iy,     0), GRID_G - 1);
    int y1 = min(max(iy + 1, 0), GRID_G - 1);
    int z0 = min(max(iz,     0), GRID_G - 1);

    int zb = min(z0, GRID_G - 2);
    int o0 = z0 - zb;                 // 0 normally, 1 at z-top boundary

    float cu0 = 1.0f - u, cv0 = 1.0f - v, cw0 = 1.0f - w;

    float ck0s[4], ck1s[4];
    ck0s[0] = cu0 * cv0 * cw0;  ck1s[0] = cu0 * cv0 * w;   // (x0,y0)
    ck0s[1] = u   * cv0 * cw0;  ck1s[1] = u   * cv0 * w;   // (x1,y0)
    ck0s[2] = cu0 * v   * cw0;  ck1s[2] = cu0 * v   * w;   // (x0,y1)
    ck0s[3] = u   * v   * cw0;  ck1s[3] = u   * v   * w;   // (x1,y1)

    int base_t = ti * (GRID_G * GRID_G * GRID_G);
    int bx0 = base_t + x0 * (GRID_G * GRID_G);
    int bx1 = base_t + x1 * (GRID_G * GRID_G);
    int bs[4];
    bs[0] = bx0 + y0 * GRID_G;
    bs[1] = bx1 + y0 * GRID_G;
    bs[2] = bx0 + y1 * GRID_G;
    bs[3] = bx1 + y1 * GRID_G;

    float sw = 1.0f - __expf(-sigma);
    float scale = lr * sw;

    float val0 = 0.0f, val1 = 0.0f, val2 = 0.0f;

#pragma unroll
    for (int half = 0; half < 2; half++) {
        // ---- Phase A: batch loads for 2 windows ----
        float4 W[2][2];
        float  w8_[2];
        int    base_[2], off_[2];
        bool   fast_[2];
#pragma unroll
        for (int s = 0; s < 2; s++) {
            int p = 2 * half + s;
            int e    = (bs[p] + zb) * 3;
            int base = e & ~3;
            int off  = e & 3;
            base_[s] = base;
            off_[s]  = off;
            bool f = (base + 12 <= VOXEL_TOTAL);
            fast_[s] = f;
            if (f) {
                const float4* wp = (const float4*)(voxel + base);
                W[s][0] = __ldg(wp + 0);
                W[s][1] = __ldg(wp + 1);
                w8_[s] = (off == 3) ? __ldg(voxel + base + 8) : 0.0f;
            }
        }

        // ---- Phase B+C: math + REDs ----
#pragma unroll
        for (int s = 0; s < 2; s++) {
            int p = 2 * half + s;
            int base = base_[s];
            int off  = off_[s];
            int e    = base + off;
            bool b0 = (off & 1) != 0;
            bool b1 = (off & 2) != 0;

            float v0x, v0y, v0z, v1x, v1y, v1z;
            if (fast_[s]) {
                float wv[9];
                wv[0] = W[s][0].x; wv[1] = W[s][0].y; wv[2] = W[s][0].z; wv[3] = W[s][0].w;
                wv[4] = W[s][1].x; wv[5] = W[s][1].y; wv[6] = W[s][1].z; wv[7] = W[s][1].w;
                wv[8] = w8_[s];
                float vj[6];
#pragma unroll
                for (int j = 0; j < 6; j++) {
                    float a  = b0 ? wv[j + 1] : wv[j];
                    float bb = b0 ? wv[j + 3] : wv[j + 2];
                    vj[j] = b1 ? bb : a;
                }
                v1x = vj[3]; v1y = vj[4]; v1z = vj[5];
                v0x = o0 ? vj[3] : vj[0];
                v0y = o0 ? vj[4] : vj[1];
                v0z = o0 ? vj[5] : vj[2];
            } else {
                int e0 = e + 3 * o0;
                v0x = __ldg(voxel + e0 + 0);
                v0y = __ldg(voxel + e0 + 1);
                v0z = __ldg(voxel + e0 + 2);
                v1x = __ldg(voxel + e + 3);
                v1y = __ldg(voxel + e + 4);
                v1z = __ldg(voxel + e + 5);
            }

            float ck0 = ck0s[p], ck1 = ck1s[p];
            val0 += ck0 * v0x + ck1 * v1x;
            val1 += ck0 * v0y + ck1 * v1y;
            val2 += ck0 * v0z + ck1 * v1z;

            float lam0 = __fdividef(1.0f, 1.0f + __expf(-scale * ck0));
            float lam1 = __fdividef(1.0f, 1.0f + __expf(-scale * ck1));

            float d00 = lam0 * (t0 - v0x), d01 = lam0 * (t1 - v0y), d02 = lam0 * (t2 - v0z);
            float d10 = lam1 * (t0 - v1x), d11 = lam1 * (t1 - v1y), d12 = lam1 * (t2 - v1z);

            float E0 = o0 ? 0.0f : d00;
            float E1 = o0 ? 0.0f : d01;
            float E2 = o0 ? 0.0f : d02;
            float E3 = o0 ? (d00 + d10) : d10;
            float E4 = o0 ? (d01 + d11) : d11;
            float E5 = o0 ? (d02 + d12) : d12;

            if (fast_[s]) {
                float E[6] = {E0, E1, E2, E3, E4, E5};
                float D[8];
#pragma unroll
                for (int j = 0; j < 8; j++) {
                    float c0 = (j <= 5)            ? E[j > 5 ? 5 : j]                 : 0.0f;
                    float c1 = (j >= 1 && j <= 6)  ? E[(j - 1) > 5 ? 5 : (j - 1)]     : 0.0f;
                    float c2 = (j >= 2 && j <= 7)  ? E[(j - 2) > 5 ? 5 : (j - 2)]     : 0.0f;
                    float c3 = (j >= 3)            ? E[(j - 3) > 5 ? 5 : (j - 3)]     : 0.0f;
                    float a  = b0 ? c1 : c0;
                    float bb = b0 ? c3 : c2;
                    D[j] = b1 ? bb : a;
                }
                float* op = out_voxel + base;
                red_add_v4f32(op + 0, D[0], D[1], D[2], D[3]);
                red_add_v4f32(op + 4, D[4], D[5], D[6], D[7]);
                if (off == 3) red_add_f32(op + 8, E5);
            } else {
                float* op = out_voxel + e;
                red_add_f32(op + 0, E0);
                red_add_f32(op + 1, E1);
                red_add_f32(op + 2, E2);
                red_add_f32(op + 3, E3);
                red_add_f32(op + 4, E4);
                red_add_f32(op + 5, E5);
            }
        }
    }

    out_value[3 * orig + 0] = val0;
    out_value[3 * orig + 1] = val1;
    out_value[3 * orig + 2] = val2;
}

// ---------------------------------------------------------------------------
// Kernel 2: bucketed main kernel — blocks walk buckets in order (L2 locality)
// ---------------------------------------------------------------------------
__global__ void __launch_bounds__(256, 5)
point_kernel_bucketed(const float* __restrict__ lr_p,
                      const float* __restrict__ voxel,
                      float* __restrict__ out_value,
                      float* __restrict__ out_voxel) {
    int g = blockIdx.x * blockDim.x + threadIdx.x;
    int b = g / BSTRIDE;
    int j = g - b * BSTRIDE;
    if (b >= NB || j >= g_cnt[b]) return;

    const float lr = __ldg(lr_p);
    float4 p4 = g_p4[g];
    float4 t4 = g_t4[g];
    int ti   = b >> 2;
    int orig = __float_as_int(t4.w);

    process_point(voxel, out_voxel, out_value,
                  p4.x, p4.y, p4.z, p4.w,
                  t4.x, t4.y, t4.z, ti, orig, lr);
}

// ---------------------------------------------------------------------------
// Fallback kernels for N > MAX_N (direct, unbucketed) + standalone copy
// ---------------------------------------------------------------------------
__global__ void voxel_copy_kernel(const float4* __restrict__ src,
                                  float4* __restrict__ dst, int n4) {
    int i = blockIdx.x * blockDim.x + threadIdx.x;
    if (i < n4) dst[i] = src[i];
}

__global__ void __launch_bounds__(256, 5)
point_kernel_direct(const int* __restrict__ t_arr,
                    const float* __restrict__ pos,
                    const float* __restrict__ lr_p,
                    const float* __restrict__ sigma_arr,
                    const float* __restrict__ tgt,
                    const float* __restrict__ voxel,
                    float* __restrict__ out_value,
                    float* __restrict__ out_voxel,
                    int N) {
    int i = blockIdx.x * blockDim.x + threadIdx.x;
    if (i >= N) return;
    const float lr = __ldg(lr_p);
    process_point(voxel, out_voxel, out_value,
                  pos[3 * i], pos[3 * i + 1], pos[3 * i + 2], sigma_arr[i],
                  tgt[3 * i], tgt[3 * i + 1], tgt[3 * i + 2],
                  t_arr[i], i, lr);
}

// ---------------------------------------------------------------------------
// Launch
// Inputs (metadata order): t, pos, lr, sigma, target_norm, voxel_array
// Output: value (N*3 f32) followed by new_voxel (T*G*G*G*3 f32)
// ---------------------------------------------------------------------------
extern "C" void kernel_launch(void* const* d_in, const int* in_sizes, int n_in,
                              void* d_out, int out_size) {
    const int*   t_arr  = (const int*)d_in[0];
    const float* pos    = (const float*)d_in[1];
    const float* lr     = (const float*)d_in[2];
    const float* sigma  = (const float*)d_in[3];
    const float* tgt    = (const float*)d_in[4];
    const float* voxel  = (const float*)d_in[5];

    const int N = in_sizes[0];
    const int voxel_elems = in_sizes[5];

    float* out_value = (float*)d_out;
    float* out_voxel = out_value + (size_t)3 * N;

    const int threads = 256;
    const int n4 = voxel_elems / 4;
    const int copy_blocks = (n4 + threads - 1) / threads;

    if (N <= MAX_N) {
        zero_cnt_kernel<<<1, 32>>>();
        {
            int SB = (N + threads - 1) / threads;
            copy_and_scatter_kernel<<<SB + copy_blocks, threads>>>(
                t_arr, pos, sigma, tgt,
                (const float4*)voxel, (float4*)out_voxel, N, SB, n4);
        }
        {
            long long total = (long long)NB * BSTRIDE;
            int blocks = (int)((total + threads - 1) / threads);
            point_kernel_bucketed<<<blocks, threads>>>(lr, voxel,
                                                       out_value, out_voxel);
        }
    } else {
        voxel_copy_kernel<<<copy_blocks, threads>>>((const float4*)voxel,
                                                    (float4*)out_voxel, n4);
        int blocks = (N + threads - 1) / threads;
        point_kernel_direct<<<blocks, threads>>>(t_arr, pos, lr, sigma, tgt,
                                                 voxel, out_value, out_voxel, N);
    }
}